// round 2
// baseline (speedup 1.0000x reference)
#include <cuda_runtime.h>
#include <cstdint>
#include <cstddef>

#define BJ      8192
#define MDIM    4096
#define KDIM    4096
#define NADPT   4
#define DR      16

// scratch: 4 fp32 partial-t buffers (8 MB) + pre-split B (4 MB)
__device__ float g_tp[4][NADPT * BJ * DR];
__device__ uint2 g_Bs[NADPT * KDIM * DR];

// ---------------------------------------------------------------------------
__device__ __forceinline__ void split_tf32(float v, uint32_t& hi, uint32_t& lo) {
    uint32_t h;
    asm("cvt.rna.tf32.f32 %0, %1;" : "=r"(h) : "f"(v));
    float r = v - __uint_as_float(h);
    asm("cvt.rna.tf32.f32 %0, %1;" : "=r"(lo) : "f"(r));
    hi = h;
}

__device__ __forceinline__ void mma8(float c[4], const uint32_t a[4], const uint32_t b[2]) {
    asm volatile(
        "mma.sync.aligned.m16n8k8.row.col.f32.tf32.tf32.f32 "
        "{%0,%1,%2,%3}, {%4,%5,%6,%7}, {%8,%9}, {%0,%1,%2,%3};\n"
        : "+f"(c[0]), "+f"(c[1]), "+f"(c[2]), "+f"(c[3])
        : "r"(a[0]), "r"(a[1]), "r"(a[2]), "r"(a[3]), "r"(b[0]), "r"(b[1]));
}

// ---------------------------------------------------------------------------
// prep: split lora_B into (hi,lo) tf32 pairs once
// ---------------------------------------------------------------------------
__global__ void split_B_kernel(const float* __restrict__ Bm) {
    int i = blockIdx.x * 256 + threadIdx.x;      // 0 .. 262143
    float v = Bm[i];
    uint2 p;
    split_tf32(v, p.x, p.y);
    g_Bs[i] = p;
}

// ---------------------------------------------------------------------------
// Stage 1: partial T over an M-chunk of 1024.
// grid (128 bj-tiles, 4 m-chunks), 128 threads = 4 warps (wm2 x wn2), warp 32x32.
// ---------------------------------------------------------------------------
__global__ __launch_bounds__(128)
void lora_stage1(const float* __restrict__ x, const float* __restrict__ Aall) {
    __shared__ float Xs[64 * 36];
    __shared__ float As[64 * 36];

    const int tid  = threadIdx.x;
    const int lane = tid & 31;
    const int warp = tid >> 5;
    const int gid  = lane >> 2;
    const int tig  = lane & 3;
    const int wm   = warp & 1;       // 2 warps over 64 bj
    const int wn   = warp >> 1;      // 2 warps over 64 nd
    const int bj0  = blockIdx.x * 64;
    const int m0   = blockIdx.y * 1024;

    const int r0 = tid >> 3;         // 0..15, rows r0 + 16*i
    const int c  = (tid & 7) * 4;    // float col within 32-chunk

    const float* xp[4];
    const float* ap[4];
#pragma unroll
    for (int i = 0; i < 4; ++i) {
        xp[i] = x    + (size_t)(bj0 + r0 + 16 * i) * MDIM + m0 + c;
        ap[i] = Aall + (size_t)(r0 + 16 * i)       * MDIM + m0 + c;
    }

    float acc[2][4][4];
#pragma unroll
    for (int i = 0; i < 2; ++i)
#pragma unroll
        for (int j = 0; j < 4; ++j)
#pragma unroll
            for (int q = 0; q < 4; ++q) acc[i][j][q] = 0.0f;

    // preload chunk 0
    float4 xv[4], av[4];
#pragma unroll
    for (int i = 0; i < 4; ++i) { xv[i] = *(const float4*)xp[i]; av[i] = *(const float4*)ap[i]; }
#pragma unroll
    for (int i = 0; i < 4; ++i) {
        *(float4*)&Xs[(r0 + 16 * i) * 36 + c] = xv[i];
        *(float4*)&As[(r0 + 16 * i) * 36 + c] = av[i];
    }
    __syncthreads();

    for (int kc = 0; kc < 1024; kc += 32) {
        const bool more = (kc + 32) < 1024;
        if (more) {
#pragma unroll
            for (int i = 0; i < 4; ++i) {
                xv[i] = *(const float4*)(xp[i] + kc + 32);
                av[i] = *(const float4*)(ap[i] + kc + 32);
            }
        }

#pragma unroll
        for (int kk = 0; kk < 32; kk += 8) {
            uint32_t ah[2][4], al[2][4], bh[4][2], bl[4][2];
#pragma unroll
            for (int mi = 0; mi < 2; ++mi) {
                const int rb = (wm * 32 + mi * 16 + gid) * 36 + kk + tig;
                split_tf32(Xs[rb],              ah[mi][0], al[mi][0]);
                split_tf32(Xs[rb + 8 * 36],     ah[mi][1], al[mi][1]);
                split_tf32(Xs[rb + 4],          ah[mi][2], al[mi][2]);
                split_tf32(Xs[rb + 8 * 36 + 4], ah[mi][3], al[mi][3]);
            }
#pragma unroll
            for (int ni = 0; ni < 4; ++ni) {
                const int cb = (wn * 32 + ni * 8 + gid) * 36 + kk + tig;
                split_tf32(As[cb],     bh[ni][0], bl[ni][0]);
                split_tf32(As[cb + 4], bh[ni][1], bl[ni][1]);
            }
#pragma unroll
            for (int mi = 0; mi < 2; ++mi)
#pragma unroll
                for (int ni = 0; ni < 4; ++ni) {
                    mma8(acc[mi][ni], ah[mi], bh[ni]);
                    mma8(acc[mi][ni], al[mi], bh[ni]);
                    mma8(acc[mi][ni], ah[mi], bl[ni]);
                }
        }
        __syncthreads();
        if (more) {
#pragma unroll
            for (int i = 0; i < 4; ++i) {
                *(float4*)&Xs[(r0 + 16 * i) * 36 + c] = xv[i];
                *(float4*)&As[(r0 + 16 * i) * 36 + c] = av[i];
            }
            __syncthreads();
        }
    }

    float* tp = g_tp[blockIdx.y];
#pragma unroll
    for (int mi = 0; mi < 2; ++mi)
#pragma unroll
        for (int ni = 0; ni < 4; ++ni) {
            const int row = bj0 + wm * 32 + mi * 16 + gid;
            const int col = wn * 32 + ni * 8 + 2 * tig;    // nd
            const int n = col >> 4, d = col & 15;
            float* dst = tp + ((size_t)(n * BJ) + row) * DR + d;
            *(float2*)dst             = make_float2(acc[mi][ni][0], acc[mi][ni][1]);
            *(float2*)(dst + 8 * DR)  = make_float2(acc[mi][ni][2], acc[mi][ni][3]);
        }
}

// ---------------------------------------------------------------------------
// Stage 2: warp-autonomous, no smem, no syncs.
// Each warp: 32 bj rows (A-frags in registers, split once) x 1024 k cols.
// B frags streamed from pre-split g_Bs (L1-resident window) with prefetch.
// grid (32 bj-groups, 4 k-segs, 4 adapters), 256 threads = 8 warps.
// ---------------------------------------------------------------------------
__global__ __launch_bounds__(256)
void lora_stage2(float* __restrict__ out) {
    const int tid  = threadIdx.x;
    const int lane = tid & 31;
    const int warp = tid >> 5;
    const int gid  = lane >> 2;
    const int tig  = lane & 3;

    const int n     = blockIdx.z;
    const int kbase = blockIdx.y * 1024;
    const int row0  = blockIdx.x * 256 + warp * 32;

    // A-frags: sum 4 partials, split once, hold in registers
    uint32_t ah[2][2][4], al[2][2][4];
#pragma unroll
    for (int mi = 0; mi < 2; ++mi)
#pragma unroll
        for (int kk = 0; kk < 2; ++kk)
#pragma unroll
            for (int q = 0; q < 4; ++q) {
                const int r = row0 + mi * 16 + gid + (q & 1) * 8;
                const int d = kk * 8 + tig + (q >> 1) * 4;
                const int idx = (n * BJ + r) * DR + d;
                float v = g_tp[0][idx] + g_tp[1][idx] + g_tp[2][idx] + g_tp[3][idx];
                split_tf32(v, ah[mi][kk][q], al[mi][kk][q]);
            }

    const uint2* Bp = g_Bs + (size_t)n * KDIM * DR;
    float* outp = out + (size_t)n * BJ * KDIM;

    uint2 bcur[2][2], bnxt[2][2];
    {
        const int r = (kbase + gid) * DR;
#pragma unroll
        for (int kk = 0; kk < 2; ++kk) {
            bcur[kk][0] = Bp[r + kk * 8 + tig];
            bcur[kk][1] = Bp[r + kk * 8 + tig + 4];
        }
    }

    for (int j = 0; j < 128; ++j) {
        const int kcol = kbase + j * 8;
        if (j + 1 < 128) {
            const int r = (kcol + 8 + gid) * DR;
#pragma unroll
            for (int kk = 0; kk < 2; ++kk) {
                bnxt[kk][0] = Bp[r + kk * 8 + tig];
                bnxt[kk][1] = Bp[r + kk * 8 + tig + 4];
            }
        }

        float c1[2][4], c2[2][4], c3[2][4];
#pragma unroll
        for (int mi = 0; mi < 2; ++mi)
#pragma unroll
            for (int q = 0; q < 4; ++q) { c1[mi][q] = 0.f; c2[mi][q] = 0.f; c3[mi][q] = 0.f; }

#pragma unroll
        for (int kk = 0; kk < 2; ++kk) {
            uint32_t bh[2] = { bcur[kk][0].x, bcur[kk][1].x };
            uint32_t bl[2] = { bcur[kk][0].y, bcur[kk][1].y };
#pragma unroll
            for (int mi = 0; mi < 2; ++mi) {
                mma8(c1[mi], ah[mi][kk], bh);
                mma8(c2[mi], al[mi][kk], bh);
                mma8(c3[mi], ah[mi][kk], bl);
            }
        }

#pragma unroll
        for (int mi = 0; mi < 2; ++mi) {
            const int row = row0 + mi * 16 + gid;
            const int col = kcol + 2 * tig;
            float v0 = c1[mi][0] + c2[mi][0] + c3[mi][0];
            float v1 = c1[mi][1] + c2[mi][1] + c3[mi][1];
            float v2 = c1[mi][2] + c2[mi][2] + c3[mi][2];
            float v3 = c1[mi][3] + c2[mi][3] + c3[mi][3];
            *(float2*)&outp[(size_t)row * KDIM + col]       = make_float2(v0, v1);
            *(float2*)&outp[(size_t)(row + 8) * KDIM + col] = make_float2(v2, v3);
        }

#pragma unroll
        for (int kk = 0; kk < 2; ++kk) { bcur[kk][0] = bnxt[kk][0]; bcur[kk][1] = bnxt[kk][1]; }
    }
}

// ---------------------------------------------------------------------------
extern "C" void kernel_launch(void* const* d_in, const int* in_sizes, int n_in,
                              void* d_out, int out_size) {
    const float* x    = (const float*)d_in[0];
    const float* Aall = (const float*)d_in[1];
    const float* Bm   = (const float*)d_in[2];
    float* out = (float*)d_out;

    split_B_kernel<<<NADPT * KDIM * DR / 256, 256>>>(Bm);
    lora_stage1<<<dim3(128, 4), 128>>>(x, Aall);
    lora_stage2<<<dim3(32, 4, 4), 256>>>(out);
}